// round 17
// baseline (speedup 1.0000x reference)
#include <cuda_runtime.h>
#include <cstdint>

// hidden[1024], enc[65536,1024], W[1024,1024], b[1024]
// out[65536] = softmax(enc @ (W^T @ hidden) + b.hidden)
// b.hidden is a uniform shift across scores -> softmax-invariant -> dropped.
//
// SINGLE persistent kernel (148 blocks = 1/SM, co-resident by construction).
// Rationale: every small kernel measured a ~5-6us floor (R7/R12/R14/R16 ncu);
// fusing all phases behind sense-reversing grid barriers removes those floors.

#define H 1024
#define S 65536
#define TILE_ROWS 64
#define NTILES (S / TILE_ROWS)   // 1024
#define NBLOCKS 148              // one block per SM
#define NTHREADS 1024            // 32 warps
#define SM_BLOCKS 16             // epilogue blocks: 16*1024*float4 = 65536

// ---- device scratch (no allocation allowed) ----
__device__ __align__(16) float g_vpart[128 * H];
__device__ __align__(16) float g_v[H];
__device__ unsigned g_maxu;
__device__ float g_psum[SM_BLOCKS];
__device__ int g_tk = 0;
__device__ int g_cnt[4];         // barrier counters (self-resetting)
__device__ unsigned g_sense[4];  // barrier sense (toggles; never reset)

// monotonic float<->uint encoding (order-preserving)
__device__ __forceinline__ unsigned enc_ord(float f) {
    unsigned u = __float_as_uint(f);
    return (u & 0x80000000u) ? ~u : (u | 0x80000000u);
}
__device__ __forceinline__ float dec_ord(unsigned u) {
    return (u & 0x80000000u) ? __uint_as_float(u ^ 0x80000000u)
                             : __uint_as_float(~u);
}

// Sense-reversing grid barrier (call from tid==0 only). Last arriver zeroes
// the counter (and does per-replay resets for id==1) BEFORE flipping sense,
// so the barrier is reusable across graph replays with no external reset.
__device__ __forceinline__ void gbar(int id, int n, bool wait) {
    unsigned s = *(volatile unsigned*)&g_sense[id];
    __threadfence();
    int old = atomicAdd(&g_cnt[id], 1);
    if (old == n - 1) {
        g_cnt[id] = 0;
        if (id == 1) { g_tk = 0; g_maxu = 0u; }  // pre-scores resets
        __threadfence();
        atomicExch(&g_sense[id], s ^ 1u);
    } else if (wait) {
        while (*(volatile unsigned*)&g_sense[id] == s) __nanosleep(32);
        __threadfence();
    }
}

__global__ __launch_bounds__(NTHREADS, 1) void mega_kernel(
    const float* __restrict__ W, const float* __restrict__ h,
    const float* __restrict__ enc, float* __restrict__ out) {
    __shared__ __align__(16) float vs[H];
    __shared__ float part[TILE_ROWS * 33];   // stride-33 pad: conflict-free
    __shared__ float red[256];
    __shared__ float wmax[2];
    __shared__ float wsum[32];
    __shared__ float sinv;
    __shared__ int s_t;

    int tid = threadIdx.x;
    int bid = blockIdx.x;
    int warp = tid >> 5, lane = tid & 31;

    // ===== Phase 1: v partials (blocks 0..127, threads 0..255) =====
    // Block b covers W rows [8b,8b+8); thread owns one float4 column group.
    if (bid < 128 && tid < 256) {
        int i0 = bid * 8;
        const float4* W4 = (const float4*)W;
        float hr[8];
#pragma unroll
        for (int r = 0; r < 8; r++) hr[r] = __ldg(&h[i0 + r]);
        float4 w[8];
#pragma unroll
        for (int r = 0; r < 8; r++) w[r] = W4[(size_t)(i0 + r) * 256 + tid];
        float4 a0 = make_float4(0.f, 0.f, 0.f, 0.f);
        float4 a1 = make_float4(0.f, 0.f, 0.f, 0.f);
#pragma unroll
        for (int r = 0; r < 8; r += 2) {
            a0.x = fmaf(w[r].x, hr[r], a0.x);
            a0.y = fmaf(w[r].y, hr[r], a0.y);
            a0.z = fmaf(w[r].z, hr[r], a0.z);
            a0.w = fmaf(w[r].w, hr[r], a0.w);
            a1.x = fmaf(w[r + 1].x, hr[r + 1], a1.x);
            a1.y = fmaf(w[r + 1].y, hr[r + 1], a1.y);
            a1.z = fmaf(w[r + 1].z, hr[r + 1], a1.z);
            a1.w = fmaf(w[r + 1].w, hr[r + 1], a1.w);
        }
        float4 acc = make_float4(a0.x + a1.x, a0.y + a1.y,
                                 a0.z + a1.z, a0.w + a1.w);
        ((float4*)g_vpart)[bid * 256 + tid] = acc;
        __threadfence();                      // my stores -> global visibility
    }
    __syncthreads();
    if (tid == 0) gbar(0, NBLOCKS, true);
    __syncthreads();

    // ===== Phase 2: reduce 128 partials/col -> g_v (blocks 0..31) =====
    if (bid < 32 && tid < 256) {
        int col = bid * 32 + (tid >> 3);
        int sub = tid & 7;
        float s0 = 0.f, s1 = 0.f;
#pragma unroll
        for (int i = 0; i < 16; i += 2) {
            s0 += g_vpart[(sub * 16 + i) * H + col];
            s1 += g_vpart[(sub * 16 + i + 1) * H + col];
        }
        red[tid] = s0 + s1;
    }
    __syncthreads();
    if (bid < 32 && tid < 256 && (tid & 7) == 0) {
        float s = 0.f;
#pragma unroll
        for (int k = 0; k < 8; k++) s += red[tid + k];   // fixed order
        g_v[bid * 32 + (tid >> 3)] = s;
        __threadfence();
    }
    __syncthreads();
    if (tid == 0) gbar(1, NBLOCKS, true);     // releases with g_tk/g_maxu reset
    __syncthreads();

    // ===== Phase 3: scores = enc . v (persistent ticket loop) =====
    if (tid < 256) ((float4*)vs)[tid] = ((const float4*)g_v)[tid];
    const float4* enc4 = (const float4*)enc;
    const float4* vs4 = (const float4*)vs;

    for (;;) {
        if (tid == 0) s_t = atomicAdd(&g_tk, 1);
        __syncthreads();                      // s_t valid; vs/part coherent
        int t = s_t;
        if (t >= NTILES) break;
        int row0 = t * TILE_ROWS + warp * 2;

#pragma unroll
        for (int r = 0; r < 2; r++) {
            const float4* p = enc4 + (size_t)(row0 + r) * (H / 4) + lane;
            float acc0 = 0.f, acc1 = 0.f;
#pragma unroll
            for (int k = 0; k < 8; k += 2) {
                float4 e0 = __ldcs(p + k * 32);   // streaming: no L2 pollute
                float4 e1 = __ldcs(p + (k + 1) * 32);
                float4 v0 = vs4[k * 32 + lane];
                float4 v1 = vs4[(k + 1) * 32 + lane];
                acc0 = fmaf(e0.x, v0.x, acc0);
                acc0 = fmaf(e0.y, v0.y, acc0);
                acc0 = fmaf(e0.z, v0.z, acc0);
                acc0 = fmaf(e0.w, v0.w, acc0);
                acc1 = fmaf(e1.x, v1.x, acc1);
                acc1 = fmaf(e1.y, v1.y, acc1);
                acc1 = fmaf(e1.z, v1.z, acc1);
                acc1 = fmaf(e1.w, v1.w, acc1);
            }
            part[(warp * 2 + r) * 33 + lane] = acc0 + acc1;
        }
        __syncthreads();

        if (tid < TILE_ROWS) {
            float s = 0.f;
#pragma unroll
            for (int k = 0; k < 32; k++) s += part[tid * 33 + k];  // fixed order
            out[t * TILE_ROWS + tid] = s;                          // coalesced
            float m = s;
#pragma unroll
            for (int o = 16; o > 0; o >>= 1)
                m = fmaxf(m, __shfl_xor_sync(0xffffffffu, m, o));
            if (lane == 0) wmax[tid >> 5] = m;
        }
        __syncthreads();
        if (tid == 0)
            atomicMax(&g_maxu, enc_ord(fmaxf(wmax[0], wmax[1])));  // order-inv
    }

    // ===== barrier 2: all scores + maxes globally visible =====
    __threadfence();                          // each thread fences its stores
    __syncthreads();
    if (tid == 0) gbar(2, NBLOCKS, bid < SM_BLOCKS);
    if (bid >= SM_BLOCKS) return;             // arrived; done
    __syncthreads();                          // others wait for tid0's pass

    // ===== Phase 4: softmax epilogue (blocks 0..15, float4/thread) =====
    float gmax = dec_ord(g_maxu);
    int idx = bid * NTHREADS + tid;
    float4 s = ((float4*)out)[idx];           // L2-resident (just written)
    s.x = __expf(s.x - gmax);
    s.y = __expf(s.y - gmax);
    s.z = __expf(s.z - gmax);
    s.w = __expf(s.w - gmax);

    float l = (s.x + s.y) + (s.z + s.w);
#pragma unroll
    for (int o = 16; o > 0; o >>= 1)
        l += __shfl_xor_sync(0xffffffffu, l, o);
    if (lane == 0) wsum[warp] = l;
    __syncthreads();
    if (tid < 32) {                           // fixed pairing: deterministic
        float a = wsum[lane];
#pragma unroll
        for (int o = 16; o > 0; o >>= 1)
            a += __shfl_xor_sync(0xffffffffu, a, o);
        if (lane == 0) g_psum[bid] = a;       // tid 0
    }
    __syncthreads();
    if (tid == 0) gbar(3, SM_BLOCKS, true);   // psum writes fenced inside gbar
    __syncthreads();

    if (tid < 32) {                           // warp-parallel total, fixed pair
        float a = (lane < SM_BLOCKS) ? __ldcg(&g_psum[lane]) : 0.f;
#pragma unroll
        for (int o = 16; o > 0; o >>= 1)
            a += __shfl_xor_sync(0xffffffffu, a, o);
        if (lane == 0) sinv = 1.0f / a;
    }
    __syncthreads();

    float inv = sinv;
    s.x *= inv; s.y *= inv; s.z *= inv; s.w *= inv;
    ((float4*)out)[idx] = s;
}

extern "C" void kernel_launch(void* const* d_in, const int* in_sizes, int n_in,
                              void* d_out, int out_size) {
    const float* hidden = (const float*)d_in[0];  // [1024]
    const float* enc    = (const float*)d_in[1];  // [65536,1024]
    const float* W      = (const float*)d_in[2];  // [1024,1024]
    // d_in[3] = b : unused (softmax shift-invariant)
    float* out = (float*)d_out;                   // [65536]

    mega_kernel<<<NBLOCKS, NTHREADS>>>(W, hidden, enc, out);
}